// round 14
// baseline (speedup 1.0000x reference)
#include <cuda_runtime.h>

// ResamplerLayer: trilinear resample of [B,D,H,W,C=4] fp32 volume at
// [B,OD,OH,OW,3] continuous coords (ZERO boundary: weights from CLAMPED
// corner indices). Output [B,OD,OH,OW,4] fp32.
//
// R4:  2 lanes per point (lane bit = floor-W / ceil-W) -> adjacent 16B pair
//      coalesces into one L1tex wavefront per gather instruction.
// R6:  2 points per thread (batch 0 + batch 1, same spatial offset) -> MLP=8.
// R8:  L2 eviction policies: volume=evict_last (pin 67MB in 126MB L2),
//      coords=evict_first, stores=st.global.cs.
// R9/R11: (256,8), 32 regs, ~88% occ. R12 (.cg) regressed -> back to .nc.
// R13: warp-cooperative coord loading. A warp's 16 points per batch need 48
//      contiguous floats; load them as two full-warp contiguous 128B loads
//      (A=base[lane], B=base[16+lane]) and redistribute via shfl. Coord
//      wavefronts ~15 -> ~7 per warp (of ~163 total: gathers 144, stores 4).

#define Bk   2
#define Dk   128
#define Hk   128
#define Wk   128
#define ODk  96
#define OHk  96
#define OWk  96

#define NPTS (Bk * ODk * OHk * OWk)          // 1,769,472
#define PTS_PER_BATCH (ODk * OHk * OWk)      // 884,736 == NPTS/2
#define VOLSZ (Dk * Hk * Wk)
#define FULLMASK 0xffffffffu

__device__ __forceinline__ unsigned long long pol_evict_last() {
    unsigned long long p;
    asm("createpolicy.fractional.L2::evict_last.b64 %0, 1.0;" : "=l"(p));
    return p;
}

__device__ __forceinline__ unsigned long long pol_evict_first() {
    unsigned long long p;
    asm("createpolicy.fractional.L2::evict_first.b64 %0, 1.0;" : "=l"(p));
    return p;
}

// Volume gather: non-coherent, L2 evict_last (pin volume in L2).
__device__ __forceinline__ float4 ldg_vol(const float4* p, unsigned long long pol) {
    float4 v;
    asm("ld.global.nc.L2::cache_hint.v4.f32 {%0,%1,%2,%3}, [%4], %5;"
        : "=f"(v.x), "=f"(v.y), "=f"(v.z), "=f"(v.w)
        : "l"(p), "l"(pol));
    return v;
}

// Coord flat load: streaming (evict_first).
__device__ __forceinline__ float ldg_coord(const float* p, unsigned long long pol) {
    float v;
    asm("ld.global.nc.L2::cache_hint.f32 %0, [%1], %2;"
        : "=f"(v) : "l"(p), "l"(pol));
    return v;
}

// Output store: cache-streaming.
__device__ __forceinline__ void stg_out(float4* p, float4 v) {
    asm volatile("st.global.cs.v4.f32 [%0], {%1,%2,%3,%4};"
                 :: "l"(p), "f"(v.x), "f"(v.y), "f"(v.z), "f"(v.w) : "memory");
}

__device__ __forceinline__ float4 f4_fma2(float4 a, float wa, float4 b, float wb) {
    float4 r;
    r.x = fmaf(a.x, wa, b.x * wb);
    r.y = fmaf(a.y, wa, b.y * wb);
    r.z = fmaf(a.z, wa, b.z * wb);
    r.w = fmaf(a.w, wa, b.w * wb);
    return r;
}

// Pick flat coord float i (0..47) out of the cooperative pair (A covers
// 0..31 from lane index, B covers 16..47 from lane index-16).
__device__ __forceinline__ float coord_pick(float A, float B, int i) {
    float va = __shfl_sync(FULLMASK, A, i & 31);
    float vb = __shfl_sync(FULLMASK, B, (i - 16) & 31);
    return (i < 32) ? va : vb;
}

struct PtAddr {
    const float4* q;   // volume base + batch + this lane's W
    int rFF, rCF, rFC, rCC;
    float w0d, w1d, w0h, w1h, w0w, w1w;
};

__device__ __forceinline__ PtAddr make_addr(const float4* __restrict__ vol,
                                            float cd, float ch, float cw,
                                            int batch_base, int s) {
    int fd0 = (int)floorf(cd);
    int fh0 = (int)floorf(ch);
    int fw0 = (int)floorf(cw);

    int fd  = min(max(fd0,     0), Dk - 1);
    int fh  = min(max(fh0,     0), Hk - 1);
    int fw  = min(max(fw0,     0), Wk - 1);
    int cdI = min(max(fd0 + 1, 0), Dk - 1);
    int chI = min(max(fh0 + 1, 0), Hk - 1);
    int cwI = min(max(fw0 + 1, 0), Wk - 1);

    PtAddr a;
    a.w0d = cd - (float)fd;    a.w1d = (float)cdI - cd;
    a.w0h = ch - (float)fh;    a.w1h = (float)chI - ch;
    a.w0w = cw - (float)fw;    a.w1w = (float)cwI - cw;

    int wsel = s ? cwI : fw;
    a.q = vol + batch_base + wsel;
    a.rFF = (fd  * Hk + fh ) * Wk;
    a.rCF = (cdI * Hk + fh ) * Wk;
    a.rFC = (fd  * Hk + chI) * Wk;
    a.rCC = (cdI * Hk + chI) * Wk;
    return a;
}

__global__ __launch_bounds__(256, 8)
void resampler_kernel(const float4* __restrict__ vol,     // [B,D,H,W] of float4
                      const float*  __restrict__ coords,  // [NPTS,3]
                      float4*       __restrict__ out)     // [NPTS] of float4
{
    unsigned long long polL = pol_evict_last();
    unsigned long long polF = pol_evict_first();

    int t    = blockIdx.x * blockDim.x + threadIdx.x;     // exact-fit grid
    int lane = threadIdx.x & 31;
    int s    = t & 1;                                     // 0 = floor-W, 1 = ceil-W
    int q    = t >> 1;                                    // point (batch 0)
    int q_base = (t & ~31) >> 1;                          // warp's first point

    // Warp-cooperative coord load: 48 contiguous floats per batch, as two
    // full-warp 128B-spans (A: floats 0..31, B: floats 16..47).
    const float* base0 = coords + (size_t)q_base * 3;
    const float* base1 = coords + ((size_t)q_base + PTS_PER_BATCH) * 3;
    float A0 = ldg_coord(base0 + lane, polF);
    float B0 = ldg_coord(base0 + 16 + lane, polF);
    float A1 = ldg_coord(base1 + lane, polF);
    float B1 = ldg_coord(base1 + 16 + lane, polF);

    int j  = lane >> 1;          // pair-local point index 0..15
    int i0 = j * 3;              // flat float index of this point's cd

    float cd0 = coord_pick(A0, B0, i0);
    float ch0 = coord_pick(A0, B0, i0 + 1);
    float cw0 = coord_pick(A0, B0, i0 + 2);
    float cd1 = coord_pick(A1, B1, i0);
    float ch1 = coord_pick(A1, B1, i0 + 1);
    float cw1 = coord_pick(A1, B1, i0 + 2);

    int p0 = q;                    // batch 0
    int p1 = q + PTS_PER_BATCH;    // batch 1 (same spatial offset)

    PtAddr a0 = make_addr(vol, cd0, ch0, cw0, 0,     s);
    PtAddr a1 = make_addr(vol, cd1, ch1, cw1, VOLSZ, s);

    // 8 gathers back-to-back: MLP=8 per lane; lane pairs share 128B lines.
    float4 s0FF = ldg_vol(a0.q + a0.rFF, polL);
    float4 s0CF = ldg_vol(a0.q + a0.rCF, polL);
    float4 s0FC = ldg_vol(a0.q + a0.rFC, polL);
    float4 s0CC = ldg_vol(a0.q + a0.rCC, polL);
    float4 s1FF = ldg_vol(a1.q + a1.rFF, polL);
    float4 s1CF = ldg_vol(a1.q + a1.rCF, polL);
    float4 s1FC = ldg_vol(a1.q + a1.rFC, polL);
    float4 s1CC = ldg_vol(a1.q + a1.rCC, polL);

    // Point 0: bilinear H,D at fixed W, exchange, W-blend.
    float4 e0 = f4_fma2(s0FF, a0.w1h, s0FC, a0.w0h);
    float4 e1 = f4_fma2(s0CF, a0.w1h, s0CC, a0.w0h);
    float4 c0 = f4_fma2(e0, a0.w1d, e1, a0.w0d);

    float4 o0;
    o0.x = __shfl_xor_sync(FULLMASK, c0.x, 1);
    o0.y = __shfl_xor_sync(FULLMASK, c0.y, 1);
    o0.z = __shfl_xor_sync(FULLMASK, c0.z, 1);
    o0.w = __shfl_xor_sync(FULLMASK, c0.w, 1);

    // Point 1.
    float4 f0 = f4_fma2(s1FF, a1.w1h, s1FC, a1.w0h);
    float4 f1 = f4_fma2(s1CF, a1.w1h, s1CC, a1.w0h);
    float4 c1 = f4_fma2(f0, a1.w1d, f1, a1.w0d);

    float4 o1;
    o1.x = __shfl_xor_sync(FULLMASK, c1.x, 1);
    o1.y = __shfl_xor_sync(FULLMASK, c1.y, 1);
    o1.z = __shfl_xor_sync(FULLMASK, c1.z, 1);
    o1.w = __shfl_xor_sync(FULLMASK, c1.w, 1);

    if (s == 0) {
        stg_out(out + p0, f4_fma2(c0, a0.w1w, o0, a0.w0w));
        stg_out(out + p1, f4_fma2(c1, a1.w1w, o1, a1.w0w));
    }
}

extern "C" void kernel_launch(void* const* d_in, const int* in_sizes, int n_in,
                              void* d_out, int out_size) {
    const float4* vol    = (const float4*)d_in[0];   // inputs [B,D,H,W,4] fp32
    const float*  coords = (const float*)d_in[1];    // sample_coords [B,OD,OH,OW,3]
    float4*       out    = (float4*)d_out;

    const int threads = 256;
    const int blocks  = NPTS / threads;              // NPTS threads total, exact fit
    resampler_kernel<<<blocks, threads>>>(vol, coords, out);
}

// round 15
// speedup vs baseline: 1.0073x; 1.0073x over previous
#include <cuda_runtime.h>

// ResamplerLayer: trilinear resample of [B,D,H,W,C=4] fp32 volume at
// [B,OD,OH,OW,3] continuous coords (ZERO boundary: weights from CLAMPED
// corner indices). Output [B,OD,OH,OW,4] fp32.
//
// Final configuration (best measured: 39.39us). Techniques:
// R4:  2 lanes per point (lane bit = floor-W / ceil-W) -> adjacent 16B pair
//      coalesces into one L1tex wavefront per gather instruction
//      (~4.5 lines/point instead of 8).
// R6:  2 points per thread (batch 0 + batch 1, same spatial offset) -> 8
//      independent gathers in flight per lane (MLP=8).
// R8:  L2 eviction policies: volume=evict_last (pin 67MB volume in 126MB
//      L2 across graph replays), coords=evict_first, stores=st.global.cs.
// R9:  __launch_bounds__(256,7) -> 32 regs.
// R12/R13 experiments (.cg bypass, coop coord loads, 8 CTAs/SM) were all
//      neutral-or-worse: the kernel sits on the L1tex random-gather
//      wavefront floor (~144 gather wavefronts/warp @ ~1 wf/cyc/SM),
//      which is intrinsic to the [.,W,C] layout with random coords.

#define Bk   2
#define Dk   128
#define Hk   128
#define Wk   128
#define ODk  96
#define OHk  96
#define OWk  96

#define NPTS (Bk * ODk * OHk * OWk)          // 1,769,472
#define PTS_PER_BATCH (ODk * OHk * OWk)      // 884,736 == NPTS/2
#define VOLSZ (Dk * Hk * Wk)

__device__ __forceinline__ unsigned long long pol_evict_last() {
    unsigned long long p;
    asm("createpolicy.fractional.L2::evict_last.b64 %0, 1.0;" : "=l"(p));
    return p;
}

__device__ __forceinline__ unsigned long long pol_evict_first() {
    unsigned long long p;
    asm("createpolicy.fractional.L2::evict_first.b64 %0, 1.0;" : "=l"(p));
    return p;
}

// Volume gather: non-coherent load, pinned in L2 (evict_last policy).
__device__ __forceinline__ float4 ldg_vol(const float4* p, unsigned long long pol) {
    float4 v;
    asm volatile("ld.global.nc.L2::cache_hint.v4.f32 {%0,%1,%2,%3}, [%4], %5;"
                 : "=f"(v.x), "=f"(v.y), "=f"(v.z), "=f"(v.w)
                 : "l"(p), "l"(pol));
    return v;
}

// Coord load: streaming (evict_first policy).
__device__ __forceinline__ float ldg_coord(const float* p, unsigned long long pol) {
    float v;
    asm volatile("ld.global.nc.L2::cache_hint.f32 %0, [%1], %2;"
                 : "=f"(v) : "l"(p), "l"(pol));
    return v;
}

// Output store: cache-streaming.
__device__ __forceinline__ void stg_out(float4* p, float4 v) {
    asm volatile("st.global.cs.v4.f32 [%0], {%1,%2,%3,%4};"
                 :: "l"(p), "f"(v.x), "f"(v.y), "f"(v.z), "f"(v.w) : "memory");
}

__device__ __forceinline__ float4 f4_fma2(float4 a, float wa, float4 b, float wb) {
    float4 r;
    r.x = fmaf(a.x, wa, b.x * wb);
    r.y = fmaf(a.y, wa, b.y * wb);
    r.z = fmaf(a.z, wa, b.z * wb);
    r.w = fmaf(a.w, wa, b.w * wb);
    return r;
}

struct PtAddr {
    const float4* q;   // volume base + batch + this lane's W
    int rFF, rCF, rFC, rCC;
    float w0d, w1d, w0h, w1h, w0w, w1w;
};

__device__ __forceinline__ PtAddr make_addr(const float4* __restrict__ vol,
                                            const float* __restrict__ coords,
                                            int p, int batch_base, int s,
                                            unsigned long long polF) {
    const float* cp = coords + (size_t)p * 3;
    float cd = ldg_coord(cp + 0, polF);
    float ch = ldg_coord(cp + 1, polF);
    float cw = ldg_coord(cp + 2, polF);

    int fd0 = (int)floorf(cd);
    int fh0 = (int)floorf(ch);
    int fw0 = (int)floorf(cw);

    int fd  = min(max(fd0,     0), Dk - 1);
    int fh  = min(max(fh0,     0), Hk - 1);
    int fw  = min(max(fw0,     0), Wk - 1);
    int cdI = min(max(fd0 + 1, 0), Dk - 1);
    int chI = min(max(fh0 + 1, 0), Hk - 1);
    int cwI = min(max(fw0 + 1, 0), Wk - 1);

    PtAddr a;
    a.w0d = cd - (float)fd;    a.w1d = (float)cdI - cd;
    a.w0h = ch - (float)fh;    a.w1h = (float)chI - ch;
    a.w0w = cw - (float)fw;    a.w1w = (float)cwI - cw;

    int wsel = s ? cwI : fw;
    a.q = vol + batch_base + wsel;
    a.rFF = (fd  * Hk + fh ) * Wk;
    a.rCF = (cdI * Hk + fh ) * Wk;
    a.rFC = (fd  * Hk + chI) * Wk;
    a.rCC = (cdI * Hk + chI) * Wk;
    return a;
}

__global__ __launch_bounds__(256, 7)
void resampler_kernel(const float4* __restrict__ vol,     // [B,D,H,W] of float4
                      const float*  __restrict__ coords,  // [NPTS,3]
                      float4*       __restrict__ out)     // [NPTS] of float4
{
    unsigned long long polL = pol_evict_last();
    unsigned long long polF = pol_evict_first();

    int t = blockIdx.x * blockDim.x + threadIdx.x;        // exact-fit grid
    int q = t >> 1;                                       // pair index in [0, NPTS/2)
    int s = t & 1;                                        // 0 = floor-W, 1 = ceil-W

    int p0 = q;                    // batch 0
    int p1 = q + PTS_PER_BATCH;    // batch 1 (same spatial offset)

    PtAddr a0 = make_addr(vol, coords, p0, 0,     s, polF);
    PtAddr a1 = make_addr(vol, coords, p1, VOLSZ, s, polF);

    // 8 gathers back-to-back: MLP=8 per lane; lane pairs share 128B lines.
    float4 s0FF = ldg_vol(a0.q + a0.rFF, polL);
    float4 s0CF = ldg_vol(a0.q + a0.rCF, polL);
    float4 s0FC = ldg_vol(a0.q + a0.rFC, polL);
    float4 s0CC = ldg_vol(a0.q + a0.rCC, polL);
    float4 s1FF = ldg_vol(a1.q + a1.rFF, polL);
    float4 s1CF = ldg_vol(a1.q + a1.rCF, polL);
    float4 s1FC = ldg_vol(a1.q + a1.rFC, polL);
    float4 s1CC = ldg_vol(a1.q + a1.rCC, polL);

    // Point 0: bilinear H,D at fixed W, exchange, W-blend.
    float4 e0 = f4_fma2(s0FF, a0.w1h, s0FC, a0.w0h);
    float4 e1 = f4_fma2(s0CF, a0.w1h, s0CC, a0.w0h);
    float4 c0 = f4_fma2(e0, a0.w1d, e1, a0.w0d);

    float4 o0;
    o0.x = __shfl_xor_sync(0xffffffffu, c0.x, 1);
    o0.y = __shfl_xor_sync(0xffffffffu, c0.y, 1);
    o0.z = __shfl_xor_sync(0xffffffffu, c0.z, 1);
    o0.w = __shfl_xor_sync(0xffffffffu, c0.w, 1);

    // Point 1.
    float4 f0 = f4_fma2(s1FF, a1.w1h, s1FC, a1.w0h);
    float4 f1 = f4_fma2(s1CF, a1.w1h, s1CC, a1.w0h);
    float4 c1 = f4_fma2(f0, a1.w1d, f1, a1.w0d);

    float4 o1;
    o1.x = __shfl_xor_sync(0xffffffffu, c1.x, 1);
    o1.y = __shfl_xor_sync(0xffffffffu, c1.y, 1);
    o1.z = __shfl_xor_sync(0xffffffffu, c1.z, 1);
    o1.w = __shfl_xor_sync(0xffffffffu, c1.w, 1);

    if (s == 0) {
        stg_out(out + p0, f4_fma2(c0, a0.w1w, o0, a0.w0w));
        stg_out(out + p1, f4_fma2(c1, a1.w1w, o1, a1.w0w));
    }
}

extern "C" void kernel_launch(void* const* d_in, const int* in_sizes, int n_in,
                              void* d_out, int out_size) {
    const float4* vol    = (const float4*)d_in[0];   // inputs [B,D,H,W,4] fp32
    const float*  coords = (const float*)d_in[1];    // sample_coords [B,OD,OH,OW,3]
    float4*       out    = (float4*)d_out;

    const int threads = 256;
    const int blocks  = NPTS / threads;              // NPTS threads total, exact fit
    resampler_kernel<<<blocks, threads>>>(vol, coords, out);
}